// round 1
// baseline (speedup 1.0000x reference)
#include <cuda_runtime.h>
#include <cuda_bf16.h>

// Problem constants
#define ZB 8
#define ZC 128
#define ZW 64
#define ZH 64
#define LDIM 16
#define KCODES 256
#define CDIM 8
#define NPOS (ZB * ZW * ZH)   // 32768 spatial positions
#define WHPLANE (ZW * ZH)     // 4096

typedef unsigned long long u64;

// ---- packed f32x2 helpers (sm_103a) ----
__device__ __forceinline__ u64 pk2(float lo, float hi) {
    u64 r; asm("mov.b64 %0, {%1, %2};" : "=l"(r) : "f"(lo), "f"(hi)); return r;
}
__device__ __forceinline__ void upk2(u64 p, float& lo, float& hi) {
    asm("mov.b64 {%0, %1}, %2;" : "=f"(lo), "=f"(hi) : "l"(p));
}
__device__ __forceinline__ u64 ffma2(u64 a, u64 b, u64 c) {
    u64 d; asm("fma.rn.f32x2 %0, %1, %2, %3;" : "=l"(d) : "l"(a), "l"(b), "l"(c)); return d;
}
__device__ __forceinline__ u64 fmul2(u64 a, u64 b) {
    u64 d; asm("mul.rn.f32x2 %0, %1, %2;" : "=l"(d) : "l"(a), "l"(b)); return d;
}
__device__ __forceinline__ float sqrt_ap(float x) {
    float r; asm("sqrt.approx.f32 %0, %1;" : "=f"(r) : "f"(x)); return r;
}
__device__ __forceinline__ float ex2_ap(float x) {
    float r; asm("ex2.approx.f32 %0, %1;" : "=f"(r) : "f"(x)); return r;
}

// One block = one latent l (blockIdx.y) x 256 positions (blockIdx.x).
// Each thread owns one (pos, l): loops over K=256 codes held in smem.
__global__ void __launch_bounds__(256)
sth_kernel(const float* __restrict__ z, const float* __restrict__ codes,
           float* __restrict__ out_soft, float* __restrict__ out_hard,
           float* __restrict__ out_idx)
{
    const int l   = blockIdx.y;
    const int tid = threadIdx.x;
    const int pos = blockIdx.x * 256 + tid;

    __shared__ float4 sc[KCODES][2];   // codes[l] as 2x float4 per code
    __shared__ float  scn[KCODES];     // ||code||^2

    // Cooperative codebook load: one code per thread (256 threads == 256 codes)
    {
        const float4* cl = reinterpret_cast<const float4*>(codes) + (size_t)l * (KCODES * 2);
        float4 a = cl[2 * tid];
        float4 b = cl[2 * tid + 1];
        sc[tid][0] = a;
        sc[tid][1] = b;
        scn[tid] = a.x * a.x + a.y * a.y + a.z * a.z + a.w * a.w
                 + b.x * b.x + b.y * b.y + b.z * b.z + b.w * b.w;
    }
    __syncthreads();

    // Load this position's latent vector hv (8 channels, NCHW layout -> stride 4096)
    const int bb = pos >> 12;          // / 4096
    const int wh = pos & 4095;
    const float* zp = z + ((size_t)bb * ZC + (size_t)l * CDIM) * WHPLANE + wh;
    const float h0 = zp[0 * WHPLANE];
    const float h1 = zp[1 * WHPLANE];
    const float h2 = zp[2 * WHPLANE];
    const float h3 = zp[3 * WHPLANE];
    const float h4 = zp[4 * WHPLANE];
    const float h5 = zp[5 * WHPLANE];
    const float h6 = zp[6 * WHPLANE];
    const float h7 = zp[7 * WHPLANE];
    const float hn = h0 * h0 + h1 * h1 + h2 * h2 + h3 * h3
                   + h4 * h4 + h5 * h5 + h6 * h6 + h7 * h7;

    const u64 hp0 = pk2(h0, h1);
    const u64 hp1 = pk2(h2, h3);
    const u64 hp2 = pk2(h4, h5);
    const u64 hp3 = pk2(h6, h7);

    u64 acc0 = pk2(0.f, 0.f);
    u64 acc1 = acc0, acc2 = acc0, acc3 = acc0;
    float sume = 0.f;
    float mind = 3.4e38f;
    int   mink = 0;

    #pragma unroll 4
    for (int k = 0; k < KCODES; k++) {
        const float4 ca = sc[k][0];
        const float4 cb = sc[k][1];
        const u64 c0 = pk2(ca.x, ca.y);
        const u64 c1 = pk2(ca.z, ca.w);
        const u64 c2 = pk2(cb.x, cb.y);
        const u64 c3 = pk2(cb.z, cb.w);

        // dot(hv, code) via packed FMAs (even/odd lanes), then horizontal add
        u64 dp = ffma2(hp0, c0, ffma2(hp1, c1, ffma2(hp2, c2, fmul2(hp3, c3))));
        float de, doo;
        upk2(dp, de, doo);
        const float dot = de + doo;

        // d2 = max(||h||^2 - 2*dot + ||c||^2, 0)  (same expansion as reference)
        const float d2 = fmaxf(fmaf(dot, -2.0f, hn + scn[k]), 0.0f);

        // argmin on d2 == argmin on sqrt(d2); strict '<' keeps first (lowest k)
        if (d2 < mind) { mind = d2; mink = k; }

        const float dist = sqrt_ap(d2);
        const float e = ex2_ap(dist * -1.4426950408889634f);   // exp(-dist)
        sume += e;

        const u64 ep = pk2(e, e);
        acc0 = ffma2(ep, c0, acc0);
        acc1 = ffma2(ep, c1, acc1);
        acc2 = ffma2(ep, c2, acc2);
        acc3 = ffma2(ep, c3, acc3);
    }

    const float inv = 1.0f / sume;
    float a0, a1, a2, a3, a4, a5, a6, a7;
    upk2(acc0, a0, a1);
    upk2(acc1, a2, a3);
    upk2(acc2, a4, a5);
    upk2(acc3, a6, a7);

    // soft: (B,W,H,C) with c = l*8 + cd -> offset pos*128 + l*8 (32B-aligned)
    {
        float4* sp = reinterpret_cast<float4*>(out_soft + (size_t)pos * ZC + (size_t)l * CDIM);
        sp[0] = make_float4(a0 * inv, a1 * inv, a2 * inv, a3 * inv);
        sp[1] = make_float4(a4 * inv, a5 * inv, a6 * inv, a7 * inv);
    }
    if (out_hard) {
        float4* hp = reinterpret_cast<float4*>(out_hard + (size_t)pos * ZC + (size_t)l * CDIM);
        hp[0] = sc[mink][0];
        hp[1] = sc[mink][1];
    }
    if (out_idx) {
        out_idx[(size_t)pos * LDIM + l] = (float)mink;
    }
}

extern "C" void kernel_launch(void* const* d_in, const int* in_sizes, int n_in,
                              void* d_out, int out_size) {
    const float* z     = (const float*)d_in[0];
    const float* codes = (const float*)d_in[1];
    float* out = (float*)d_out;

    const long long softN = (long long)NPOS * ZC;   // 4,194,304
    const long long idxN  = (long long)NPOS * LDIM; // 524,288

    float* soft = out;
    float* hard = ((long long)out_size >= 2 * softN) ? out + softN : nullptr;
    float* idxo = ((long long)out_size >= 2 * softN + idxN) ? out + 2 * softN : nullptr;

    dim3 grid(NPOS / 256, LDIM);
    sth_kernel<<<grid, 256>>>(z, codes, soft, hard, idxo);
}

// round 2
// speedup vs baseline: 1.0320x; 1.0320x over previous
#include <cuda_runtime.h>
#include <cuda_bf16.h>

// Problem constants
#define ZB 8
#define ZC 128
#define ZW 64
#define ZH 64
#define LDIM 16
#define KCODES 256
#define CDIM 8
#define NPOS (ZB * ZW * ZH)   // 32768 spatial positions
#define WHPLANE (ZW * ZH)     // 4096

typedef unsigned long long u64;

// log2(e)^2 and -2*log2(e)^2
#define S1 2.0813689810056077f
#define S2n (-4.1627379620112154f)
// 1/S2n (applied at the end to un-scale the accumulated soft vector)
#define INV_S2n (-0.24022650695910071f)

// ---- packed f32x2 helpers (sm_103a) ----
__device__ __forceinline__ u64 pk2(float lo, float hi) {
    u64 r; asm("mov.b64 %0, {%1, %2};" : "=l"(r) : "f"(lo), "f"(hi)); return r;
}
__device__ __forceinline__ void upk2(u64 p, float& lo, float& hi) {
    asm("mov.b64 {%0, %1}, %2;" : "=f"(lo), "=f"(hi) : "l"(p));
}
__device__ __forceinline__ u64 ffma2(u64 a, u64 b, u64 c) {
    u64 d; asm("fma.rn.f32x2 %0, %1, %2, %3;" : "=l"(d) : "l"(a), "l"(b), "l"(c)); return d;
}
__device__ __forceinline__ float sqrt_ap(float x) {
    float r; asm("sqrt.approx.f32 %0, %1;" : "=f"(r) : "f"(x)); return r;
}
__device__ __forceinline__ float ex2_ap(float x) {
    float r; asm("ex2.approx.f32 %0, %1;" : "=f"(r) : "f"(x)); return r;
}

// One block = one latent l (blockIdx.y) x 256 positions (blockIdx.x).
// Each thread owns one (pos, l): loops over K=256 codes held in smem.
__global__ void __launch_bounds__(256, 5)
sth_kernel(const float* __restrict__ z, const float* __restrict__ codes,
           float* __restrict__ out_soft, float* __restrict__ out_hard,
           float* __restrict__ out_idx)
{
    const int l   = blockIdx.y;
    const int tid = threadIdx.x;
    const int pos = blockIdx.x * 256 + tid;

    __shared__ ulonglong2 sco[KCODES][2];  // original codes (for hard output), packed f32x2
    __shared__ ulonglong2 sc2[KCODES][2];  // codes scaled by S2n = -2*log2e^2 (dot + soft acc)
    __shared__ float      scn[KCODES];     // ||code||^2 * log2e^2

    // Cooperative codebook load: one code per thread (256 threads == 256 codes)
    {
        const float4* cl = reinterpret_cast<const float4*>(codes) + (size_t)l * (KCODES * 2);
        float4 a = cl[2 * tid];
        float4 b = cl[2 * tid + 1];
        sco[tid][0] = make_ulonglong2(pk2(a.x, a.y), pk2(a.z, a.w));
        sco[tid][1] = make_ulonglong2(pk2(b.x, b.y), pk2(b.z, b.w));
        sc2[tid][0] = make_ulonglong2(pk2(S2n * a.x, S2n * a.y), pk2(S2n * a.z, S2n * a.w));
        sc2[tid][1] = make_ulonglong2(pk2(S2n * b.x, S2n * b.y), pk2(S2n * b.z, S2n * b.w));
        float cn = a.x * a.x + a.y * a.y + a.z * a.z + a.w * a.w
                 + b.x * b.x + b.y * b.y + b.z * b.z + b.w * b.w;
        scn[tid] = S1 * cn;
    }
    __syncthreads();

    // Load this position's latent vector hv (8 channels, NCHW layout -> stride 4096)
    const int bb = pos >> 12;          // / 4096
    const int wh = pos & 4095;
    const float* zp = z + ((size_t)bb * ZC + (size_t)l * CDIM) * WHPLANE + wh;
    const float h0 = zp[0 * WHPLANE];
    const float h1 = zp[1 * WHPLANE];
    const float h2 = zp[2 * WHPLANE];
    const float h3 = zp[3 * WHPLANE];
    const float h4 = zp[4 * WHPLANE];
    const float h5 = zp[5 * WHPLANE];
    const float h6 = zp[6 * WHPLANE];
    const float h7 = zp[7 * WHPLANE];
    const float hn2 = S1 * (h0 * h0 + h1 * h1 + h2 * h2 + h3 * h3
                          + h4 * h4 + h5 * h5 + h6 * h6 + h7 * h7);

    const u64 hp0 = pk2(h0, h1);
    const u64 hp1 = pk2(h2, h3);
    const u64 hp2 = pk2(h4, h5);
    const u64 hp3 = pk2(h6, h7);

    u64 acc0 = pk2(0.f, 0.f);
    u64 acc1 = acc0, acc2 = acc0, acc3 = acc0;
    float sume = 0.f;
    float mind = 3.4e38f;
    int   mink = 0;

    #pragma unroll 4
    for (int k = 0; k < KCODES; k++) {
        const ulonglong2 ca = sc2[k][0];   // (c0c1, c2c3) * S2n
        const ulonglong2 cb = sc2[k][1];   // (c4c5, c6c7) * S2n

        // d2' = log2e^2 * (||h||^2 - 2 h.c + ||c||^2), built entirely in the FMA chain
        const u64 base = pk2(scn[k], hn2);
        const u64 dp = ffma2(hp0, ca.x,
                      ffma2(hp1, ca.y,
                      ffma2(hp2, cb.x,
                      ffma2(hp3, cb.y, base))));
        float de, doo;
        upk2(dp, de, doo);
        const float d2 = de + doo;

        // argmin (exact compare; positive scale preserves ordering)
        if (d2 < mind) { mind = d2; mink = k; }

        // e = exp(-sqrt(d2_true)) = 2^(-sqrt(d2'))   (|.| folds as operand modifier)
        const float dist = sqrt_ap(fabsf(d2));
        const float e = ex2_ap(-dist);
        sume += e;

        const u64 ep = pk2(e, e);
        acc0 = ffma2(ep, ca.x, acc0);
        acc1 = ffma2(ep, ca.y, acc1);
        acc2 = ffma2(ep, cb.x, acc2);
        acc3 = ffma2(ep, cb.y, acc3);
    }

    // acc holds S2n * sum(e*c); un-scale and normalize in one factor
    const float inv = INV_S2n / sume;
    float a0, a1, a2, a3, a4, a5, a6, a7;
    upk2(acc0, a0, a1);
    upk2(acc1, a2, a3);
    upk2(acc2, a4, a5);
    upk2(acc3, a6, a7);

    // soft: (B,W,H,C) with c = l*8 + cd -> offset pos*128 + l*8 (32B-aligned)
    {
        float4* sp = reinterpret_cast<float4*>(out_soft + (size_t)pos * ZC + (size_t)l * CDIM);
        sp[0] = make_float4(a0 * inv, a1 * inv, a2 * inv, a3 * inv);
        sp[1] = make_float4(a4 * inv, a5 * inv, a6 * inv, a7 * inv);
    }
    if (out_hard) {
        ulonglong2* hp = reinterpret_cast<ulonglong2*>(out_hard + (size_t)pos * ZC + (size_t)l * CDIM);
        hp[0] = sco[mink][0];
        hp[1] = sco[mink][1];
    }
    if (out_idx) {
        out_idx[(size_t)pos * LDIM + l] = (float)mink;
    }
}

extern "C" void kernel_launch(void* const* d_in, const int* in_sizes, int n_in,
                              void* d_out, int out_size) {
    const float* z     = (const float*)d_in[0];
    const float* codes = (const float*)d_in[1];
    float* out = (float*)d_out;

    const long long softN = (long long)NPOS * ZC;   // 4,194,304
    const long long idxN  = (long long)NPOS * LDIM; // 524,288

    float* soft = out;
    float* hard = ((long long)out_size >= 2 * softN) ? out + softN : nullptr;
    float* idxo = ((long long)out_size >= 2 * softN + idxN) ? out + 2 * softN : nullptr;

    dim3 grid(NPOS / 256, LDIM);
    sth_kernel<<<grid, 256>>>(z, codes, soft, hard, idxo);
}

// round 3
// speedup vs baseline: 1.0790x; 1.0456x over previous
#include <cuda_runtime.h>
#include <cuda_bf16.h>

// Problem constants
#define ZB 8
#define ZC 128
#define ZW 64
#define ZH 64
#define LDIM 16
#define KCODES 256
#define CDIM 8
#define NPOS (ZB * ZW * ZH)   // 32768 spatial positions
#define WHPLANE (ZW * ZH)     // 4096

typedef unsigned long long u64;

// log2(e)^2 and -2*log2(e)^2 ; 1/S2n to un-scale the soft accumulator
#define S1 2.0813689810056077f
#define S2n (-4.1627379620112154f)
#define INV_S2n (-0.24022650695910071f)

// ---- packed f32x2 helpers (sm_103a) ----
__device__ __forceinline__ u64 pk2(float lo, float hi) {
    u64 r; asm("mov.b64 %0, {%1, %2};" : "=l"(r) : "f"(lo), "f"(hi)); return r;
}
__device__ __forceinline__ void upk2(u64 p, float& lo, float& hi) {
    asm("mov.b64 {%0, %1}, %2;" : "=f"(lo), "=f"(hi) : "l"(p));
}
__device__ __forceinline__ u64 ffma2(u64 a, u64 b, u64 c) {
    u64 d; asm("fma.rn.f32x2 %0, %1, %2, %3;" : "=l"(d) : "l"(a), "l"(b), "l"(c)); return d;
}
__device__ __forceinline__ u64 fadd2(u64 a, u64 b) {
    u64 d; asm("add.rn.f32x2 %0, %1, %2;" : "=l"(d) : "l"(a), "l"(b)); return d;
}
__device__ __forceinline__ float sqrt_ap(float x) {
    float r; asm("sqrt.approx.f32 %0, %1;" : "=f"(r) : "f"(x)); return r;
}
__device__ __forceinline__ float ex2_ap(float x) {
    float r; asm("ex2.approx.f32 %0, %1;" : "=f"(r) : "f"(x)); return r;
}

// One block = one latent l (blockIdx.y) x 256 positions (blockIdx.x).
// Each thread owns one (pos, l): loops over K=256 codes, processed in PAIRS.
// Packed f32x2 lanes hold (code 2j, code 2j+1) of the SAME channel, so the
// dot-chain delivers both d2 values without any horizontal reduction.
__global__ void __launch_bounds__(256)
sth_kernel(const float* __restrict__ z, const float* __restrict__ codes,
           float* __restrict__ out_soft, float* __restrict__ out_hard,
           float* __restrict__ out_idx)
{
    const int l   = blockIdx.y;
    const int tid = threadIdx.x;
    const int pos = blockIdx.x * 256 + tid;

    // Transposed, pre-scaled codebook: sct[j][i] = (S2n*c_i[2j], S2n*c_i[2j+1])
    __shared__ u64        sct[KCODES / 2][CDIM];   // 8 KB
    __shared__ float      scn[KCODES];             // S1*||c||^2 (pairs contiguous) 1 KB
    __shared__ ulonglong2 sco[KCODES][2];          // original codes for hard output 8 KB

    // Cooperative codebook load: one code per thread
    {
        const float4* cl = reinterpret_cast<const float4*>(codes) + (size_t)l * (KCODES * 2);
        float4 a = cl[2 * tid];
        float4 b = cl[2 * tid + 1];
        sco[tid][0] = make_ulonglong2(pk2(a.x, a.y), pk2(a.z, a.w));
        sco[tid][1] = make_ulonglong2(pk2(b.x, b.y), pk2(b.z, b.w));
        float* sf = reinterpret_cast<float*>(sct);
        const int j = tid >> 1, lane = tid & 1;
        const int base = (j * CDIM) * 2 + lane;
        sf[base +  0] = S2n * a.x;
        sf[base +  2] = S2n * a.y;
        sf[base +  4] = S2n * a.z;
        sf[base +  6] = S2n * a.w;
        sf[base +  8] = S2n * b.x;
        sf[base + 10] = S2n * b.y;
        sf[base + 12] = S2n * b.z;
        sf[base + 14] = S2n * b.w;
        scn[tid] = S1 * (a.x * a.x + a.y * a.y + a.z * a.z + a.w * a.w
                       + b.x * b.x + b.y * b.y + b.z * b.z + b.w * b.w);
    }
    __syncthreads();

    // Load this position's latent vector hv (8 channels, NCHW -> stride 4096)
    const int bb = pos >> 12;
    const int wh = pos & 4095;
    const float* zp = z + ((size_t)bb * ZC + (size_t)l * CDIM) * WHPLANE + wh;
    const float h0 = zp[0 * WHPLANE];
    const float h1 = zp[1 * WHPLANE];
    const float h2 = zp[2 * WHPLANE];
    const float h3 = zp[3 * WHPLANE];
    const float h4 = zp[4 * WHPLANE];
    const float h5 = zp[5 * WHPLANE];
    const float h6 = zp[6 * WHPLANE];
    const float h7 = zp[7 * WHPLANE];
    const float hn2 = S1 * (h0 * h0 + h1 * h1 + h2 * h2 + h3 * h3
                          + h4 * h4 + h5 * h5 + h6 * h6 + h7 * h7);

    // h duplicated into both lanes (built once; loop body has no packing for h)
    const u64 hd0 = pk2(h0, h0);
    const u64 hd1 = pk2(h1, h1);
    const u64 hd2 = pk2(h2, h2);
    const u64 hd3 = pk2(h3, h3);
    const u64 hd4 = pk2(h4, h4);
    const u64 hd5 = pk2(h5, h5);
    const u64 hd6 = pk2(h6, h6);
    const u64 hd7 = pk2(h7, h7);
    const u64 hn2p = pk2(hn2, hn2);

    // Lane-separated soft accumulators: lane0 = even codes, lane1 = odd codes
    u64 acc0 = pk2(0.f, 0.f);
    u64 acc1 = acc0, acc2 = acc0, acc3 = acc0;
    u64 acc4 = acc0, acc5 = acc0, acc6 = acc0, acc7 = acc0;
    float sume = 0.f;
    float mind = 3.4e38f;
    int   mink = 0;

    const float2* scnp = reinterpret_cast<const float2*>(scn);

    #pragma unroll 4
    for (int j = 0; j < KCODES / 2; j++) {
        const ulonglong2 q01 = reinterpret_cast<const ulonglong2*>(sct[j])[0];
        const ulonglong2 q23 = reinterpret_cast<const ulonglong2*>(sct[j])[1];
        const ulonglong2 q45 = reinterpret_cast<const ulonglong2*>(sct[j])[2];
        const ulonglong2 q67 = reinterpret_cast<const ulonglong2*>(sct[j])[3];
        const float2 sn = scnp[j];

        // d2' (both lanes) = (scn'_pair + hn'_pair) + sum_i h_i * (S2n c_i)_pair
        u64 dp = fadd2(pk2(sn.x, sn.y), hn2p);
        dp = ffma2(hd0, q01.x, dp);
        dp = ffma2(hd1, q01.y, dp);
        dp = ffma2(hd2, q23.x, dp);
        dp = ffma2(hd3, q23.y, dp);
        dp = ffma2(hd4, q45.x, dp);
        dp = ffma2(hd5, q45.y, dp);
        dp = ffma2(hd6, q67.x, dp);
        dp = ffma2(hd7, q67.y, dp);

        float d2a, d2b;
        upk2(dp, d2a, d2b);

        // argmin (exact compare on scaled d2; positive scale preserves order,
        // strict '<' and ascending k preserve first-min semantics)
        if (d2a < mind) { mind = d2a; mink = 2 * j; }
        if (d2b < mind) { mind = d2b; mink = 2 * j + 1; }

        // e = exp(-dist) = 2^(-sqrt(S1*d2))
        const float e0 = ex2_ap(-sqrt_ap(fabsf(d2a)));
        const float e1 = ex2_ap(-sqrt_ap(fabsf(d2b)));
        sume += (e0 + e1);

        const u64 ep = pk2(e0, e1);
        acc0 = ffma2(ep, q01.x, acc0);
        acc1 = ffma2(ep, q01.y, acc1);
        acc2 = ffma2(ep, q23.x, acc2);
        acc3 = ffma2(ep, q23.y, acc3);
        acc4 = ffma2(ep, q45.x, acc4);
        acc5 = ffma2(ep, q45.y, acc5);
        acc6 = ffma2(ep, q67.x, acc6);
        acc7 = ffma2(ep, q67.y, acc7);
    }

    // Horizontal add of the two lane-accumulators, un-scale, normalize
    const float inv = INV_S2n / sume;
    float lo, hi, s0, s1, s2, s3, s4, s5, s6, s7;
    upk2(acc0, lo, hi); s0 = (lo + hi) * inv;
    upk2(acc1, lo, hi); s1 = (lo + hi) * inv;
    upk2(acc2, lo, hi); s2 = (lo + hi) * inv;
    upk2(acc3, lo, hi); s3 = (lo + hi) * inv;
    upk2(acc4, lo, hi); s4 = (lo + hi) * inv;
    upk2(acc5, lo, hi); s5 = (lo + hi) * inv;
    upk2(acc6, lo, hi); s6 = (lo + hi) * inv;
    upk2(acc7, lo, hi); s7 = (lo + hi) * inv;

    // soft: (B,W,H,C) with c = l*8 + cd -> offset pos*128 + l*8 (32B-aligned)
    {
        float4* sp = reinterpret_cast<float4*>(out_soft + (size_t)pos * ZC + (size_t)l * CDIM);
        sp[0] = make_float4(s0, s1, s2, s3);
        sp[1] = make_float4(s4, s5, s6, s7);
    }
    if (out_hard) {
        ulonglong2* hp = reinterpret_cast<ulonglong2*>(out_hard + (size_t)pos * ZC + (size_t)l * CDIM);
        hp[0] = sco[mink][0];
        hp[1] = sco[mink][1];
    }
    if (out_idx) {
        out_idx[(size_t)pos * LDIM + l] = (float)mink;
    }
}

extern "C" void kernel_launch(void* const* d_in, const int* in_sizes, int n_in,
                              void* d_out, int out_size) {
    const float* z     = (const float*)d_in[0];
    const float* codes = (const float*)d_in[1];
    float* out = (float*)d_out;

    const long long softN = (long long)NPOS * ZC;   // 4,194,304
    const long long idxN  = (long long)NPOS * LDIM; // 524,288

    float* soft = out;
    float* hard = ((long long)out_size >= 2 * softN) ? out + softN : nullptr;
    float* idxo = ((long long)out_size >= 2 * softN + idxN) ? out + 2 * softN : nullptr;

    dim3 grid(NPOS / 256, LDIM);
    sth_kernel<<<grid, 256>>>(z, codes, soft, hard, idxo);
}